// round 11
// baseline (speedup 1.0000x reference)
#include <cuda_runtime.h>
#include <cuda_bf16.h>
#include <cstdint>

// MaxUnpooling2D scatter-add.
//   updates/mask: [B=16, H=128, W=128, C=64]  -> 16,777,216 elements
//   output:       [B=16, OH=256, OW=256, C=64] -> 67,108,864 floats (268 MB)
// out_idx = (b<<22) | (mask & ~63) | c   (channel comes from the source element)
//
// R11: R6/R10's proven recipe (phased zero->scatter, scatter blocks first,
// 1 quad/thread scatter, 1 float4/thread STG zero, regs ~20), with a
// TAPERED pipeline: units [0],[1,2],[3,4],...,[13,14],[15].
// The fully-serial end caps (prologue zero, epilogue scatter) are halved;
// the steady state (2-batch units, L2-resident) is unchanged.
//   launches: zero(u0) + 8x fused + scatter(u8) = 10

static constexpr int B_DIM      = 16;
static constexpr int HWC        = 1 << 20;                    // elems per batch
static constexpr int OUT_PER_B  = 1 << 22;                    // out floats per batch

static constexpr int THREADS    = 256;

static constexpr int SQ_PER_B   = HWC / 4;                    // 262,144 quads (1<<18)
static constexpr int SB_PER_B   = SQ_PER_B / THREADS;         // 1024 scatter blocks / batch
static constexpr int ZB_PER_B   = (OUT_PER_B / 4) / THREADS;  // 4096 zero blocks / batch

// ---------------------------------------------------------------------------
// Scatter a unit (1 or 2 batches; grid size selects coverage).
// Pointers pre-offset to unit start. Works for any unit size because input is
// contiguous: q>>18 = batch within unit, base = (q>>18)<<22.
__device__ __forceinline__ void scatter_unit(const float4* __restrict__ upd4,
                                             const int4*   __restrict__ msk4,
                                             float* __restrict__ out,
                                             int sblk)
{
    int q  = sblk * THREADS + threadIdx.x;  // quad index in unit
    int i  = q << 2;                        // element index in unit
    int bl = q >> 18;                       // batch within unit
    int c  = i & 63;                        // channel of first lane

    float4 u = __ldcs(&upd4[q]);
    int4   m = __ldcs(&msk4[q]);

    int base = bl << 22;                    // batch-local output offset

    atomicAdd(&out[base | (m.x & ~63) | (c + 0)], u.x);
    atomicAdd(&out[base | (m.y & ~63) | (c + 1)], u.y);
    atomicAdd(&out[base | (m.z & ~63) | (c + 2)], u.z);
    atomicAdd(&out[base | (m.w & ~63) | (c + 3)], u.w);
}

__device__ __forceinline__ void zero_unit(float4* __restrict__ out4, int zblk)
{
    out4[zblk * THREADS + threadIdx.x] = make_float4(0.f, 0.f, 0.f, 0.f);
}

// ---------------------------------------------------------------------------
__global__ void __launch_bounds__(THREADS)
zero_kernel(float4* __restrict__ out4)
{
    zero_unit(out4, blockIdx.x);
}

// Fused: scatter current unit (blocks [0, s_blocks)) then zero next unit
// (blocks [s_blocks, s_blocks+z_blocks)). Scatter-first block order.
__global__ void __launch_bounds__(THREADS)
scatter_zero_kernel(const float4* __restrict__ upd4,
                    const int4*   __restrict__ msk4,
                    float* __restrict__ out_u,
                    float4* __restrict__ out4_next,
                    int s_blocks)
{
    int blk = blockIdx.x;
    if (blk < s_blocks) {
        scatter_unit(upd4, msk4, out_u, blk);
    } else {
        zero_unit(out4_next, blk - s_blocks);
    }
}

__global__ void __launch_bounds__(THREADS)
scatter_kernel(const float4* __restrict__ upd4,
               const int4*   __restrict__ msk4,
               float* __restrict__ out_u)
{
    scatter_unit(upd4, msk4, out_u, blockIdx.x);
}

// ---------------------------------------------------------------------------
extern "C" void kernel_launch(void* const* d_in, const int* in_sizes, int n_in,
                              void* d_out, int out_size)
{
    const float4* upd4 = (const float4*)d_in[0];
    const int4*   msk4 = (const int4*)d_in[1];
    float*        out  = (float*)d_out;

    // Unit boundaries (start batch of each unit): [0],[1,2],...,[13,14],[15]
    const int NUNITS = 9;
    const int u_start[NUNITS + 1] = {0, 1, 3, 5, 7, 9, 11, 13, 15, 16};

    // Prologue: zero unit 0 (1 batch).
    zero_kernel<<<ZB_PER_B, THREADS>>>((float4*)out);

    // Steady state: fused scatter(u) + zero(u+1).
    for (int u = 0; u < NUNITS - 1; u++) {
        int b0      = u_start[u];
        int nb      = u_start[u + 1] - b0;          // batches in this unit
        int nb_next = u_start[u + 2] - u_start[u + 1];
        int s_blocks = nb * SB_PER_B;
        int z_blocks = nb_next * ZB_PER_B;

        scatter_zero_kernel<<<s_blocks + z_blocks, THREADS>>>(
            upd4 + (size_t)b0 * SQ_PER_B,
            msk4 + (size_t)b0 * SQ_PER_B,
            out  + (size_t)b0 * OUT_PER_B,
            (float4*)(out + (size_t)u_start[u + 1] * OUT_PER_B),
            s_blocks);
    }

    // Epilogue: scatter last unit (1 batch).
    int bl = u_start[NUNITS - 1];
    scatter_kernel<<<(u_start[NUNITS] - bl) * SB_PER_B, THREADS>>>(
        upd4 + (size_t)bl * SQ_PER_B,
        msk4 + (size_t)bl * SQ_PER_B,
        out  + (size_t)bl * OUT_PER_B);
}